// round 3
// baseline (speedup 1.0000x reference)
#include <cuda_runtime.h>

#define Hh 128
#define Ww 128
#define NB 32
#define CCH 16
#define NITER 30

#define TW 32
#define TH 16
#define IW 34
#define IH 18
#define IWP 35   // padded smem row

typedef unsigned long long ULL;

// persistent state (no allocation allowed) — double buffered to avoid intra-launch RAW race
__device__ float g_bufA[NB*CCH*Hh*Ww];
__device__ float g_bufB[NB*CCH*Hh*Ww];
__device__ unsigned char g_pre[NB*Hh*Ww];      // pre-mask of current iter
__device__ unsigned char g_alive[NB*Hh*Ww];    // pre & post mask (applied lazily)

__device__ __forceinline__ ULL pk2(float a, float b){
    ULL r; asm("mov.b64 %0, {%1,%2};" : "=l"(r) : "f"(a), "f"(b)); return r;
}
__device__ __forceinline__ void fma2(ULL &d, ULL a, ULL b){
    asm("fma.rn.f32x2 %0, %1, %2, %0;" : "+l"(d) : "l"(a), "l"(b));
}
__device__ __forceinline__ float lo2(ULL v){ return __uint_as_float((unsigned)v); }
__device__ __forceinline__ float hi2(ULL v){ return __uint_as_float((unsigned)(v>>32)); }
__device__ __forceinline__ ULL relu2(ULL v){
    return pk2(fmaxf(lo2(v), 0.f), fmaxf(hi2(v), 0.f));
}

// Build initial state into bufA: cell, alive = 1
__global__ void init_kernel(const float* __restrict__ inp){
    int p = blockIdx.x*blockDim.x + threadIdx.x;
    const int total = NB*CCH*Hh*Ww;
    if (p >= total) return;
    int hw = p % (Hh*Ww);
    int c  = (p / (Hh*Ww)) % CCH;
    int n  = p / (CCH*Hh*Ww);
    float v;
    if (c == 0)       v = 1.0f - inp[(n*10 + 0)*Hh*Ww + hw];
    else if (c <= 10) v = inp[(n*10 + (c-1))*Hh*Ww + hw];
    else              v = 0.0f;
    g_bufA[p] = v;
    if (c == 0) g_alive[n*Hh*Ww + hw] = 1;
}

// Kernel 1: cell = src*alive (tile), perception + W1(relu) + W2 + residual -> dst; pre-mask byte.
__global__ void __launch_bounds__(128, 3)
step_kernel(const float* __restrict__ w1, const float* __restrict__ w2, int parity)
{
    extern __shared__ float smem[];
    float* sc = smem;                               // 16*18*35 floats
    ULL* sw1 = (ULL*)(smem + CCH*IH*IWP);           // [k][o] splatted pairs, 2304
    ULL* sw2 = sw1 + 48*48;                         // [o][j] splatted pairs, 768

    const float* __restrict__ src = parity ? g_bufB : g_bufA;
    float* __restrict__ dst       = parity ? g_bufA : g_bufB;

    const int tid = threadIdx.x;
    const int bx = blockIdx.x, by = blockIdx.y, n = blockIdx.z;
    const int gx0 = bx*TW, gy0 = by*TH;

    // w1 transposed+splatted: sw1[k*48+o] = (w1[o][k], w1[o][k])
    for (int i = tid; i < 48*48; i += 128) {
        int k = i / 48, o = i % 48;
        float w = w1[o*48 + k];
        sw1[i] = pk2(w, w);
    }
    // w2 transposed+splatted: sw2[o*16+j] = (w2[j][o], w2[j][o])
    for (int i = tid; i < 48*16; i += 128) {
        int o = i >> 4, j = i & 15;
        float w = w2[j*48 + o];
        sw2[i] = pk2(w, w);
    }
    // load masked cell tile with 1-pixel halo (zero padded)
    for (int i = tid; i < CCH*IH*IW; i += 128) {
        int sx = i % IW;
        int sy = (i / IW) % IH;
        int c  = i / (IW*IH);
        int gx = gx0 + sx - 1, gy = gy0 + sy - 1;
        float v = 0.0f;
        if (gx >= 0 && gx < Ww && gy >= 0 && gy < Hh) {
            int hw = gy*Ww + gx;
            if (g_alive[n*Hh*Ww + hw])
                v = src[((size_t)(n*CCH + c)*Hh)*Ww + hw];
        }
        sc[(c*IH + sy)*IWP + sx] = v;
    }
    __syncthreads();

    #pragma unroll 1
    for (int pass = 0; pass < 2; pass++) {
        const int pp = tid + pass*128;     // 0..255 pixel-pairs
        const int r  = pp >> 4;            // tile row 0..15
        const int ix = pp & 15;            // pair index (x0 = 2*ix)
        const int sy = r + 1;
        const int sx = 2*ix + 1;

        // ---- perception: 48 packed channels (cell, sobel-x, sobel-y) ----
        ULL perc[48];
        float premax_lo = -1e30f, premax_hi = -1e30f;
        #pragma unroll
        for (int c = 0; c < CCH; c++) {
            const float* b0 = sc + (c*IH + (sy-1))*IWP + (sx-1);
            const float* b1 = b0 + IWP;
            const float* b2 = b1 + IWP;
            float a0=b0[0],a1=b0[1],a2=b0[2],a3=b0[3];
            float m0=b1[0],m1=b1[1],m2=b1[2],m3=b1[3];
            float q0=b2[0],q1=b2[1],q2=b2[2],q3=b2[3];
            float gxl = ((a2 - a0) + 2.f*(m2 - m0) + (q2 - q0)) * 0.125f;
            float gxh = ((a3 - a1) + 2.f*(m3 - m1) + (q3 - q1)) * 0.125f;
            float gyl = ((q0 - a0) + 2.f*(q1 - a1) + (q2 - a2)) * 0.125f;
            float gyh = ((q1 - a1) + 2.f*(q2 - a2) + (q3 - a3)) * 0.125f;
            perc[c]      = pk2(m1, m2);
            perc[16 + c] = pk2(gxl, gxh);
            perc[32 + c] = pk2(gyl, gyh);
            if (c == 0) {
                float t0 = fmaxf(fmaxf(a0,a1),a2);
                float t1 = fmaxf(fmaxf(m0,m1),m2);
                float t2 = fmaxf(fmaxf(q0,q1),q2);
                premax_lo = fmaxf(fmaxf(t0,t1),t2);
                float u0 = fmaxf(fmaxf(a1,a2),a3);
                float u1 = fmaxf(fmaxf(m1,m2),m3);
                float u2 = fmaxf(fmaxf(q1,q2),q3);
                premax_hi = fmaxf(fmaxf(u0,u1),u2);
            }
        }

        // ---- cur = W2 * relu(W1 * perc) + cell, fully packed f32x2 ----
        ULL cur[16];
        #pragma unroll
        for (int j = 0; j < 16; j++) cur[j] = perc[j];   // residual init

        #pragma unroll 1
        for (int ob = 0; ob < 48; ob += 4) {
            ULL a0 = 0ull, a1 = 0ull, a2 = 0ull, a3 = 0ull;
            const ULL* wp = sw1 + ob;
            #pragma unroll
            for (int k = 0; k < 48; k++) {
                ulonglong2 wA = *reinterpret_cast<const ulonglong2*>(wp + k*48);
                ulonglong2 wB = *reinterpret_cast<const ulonglong2*>(wp + k*48 + 2);
                fma2(a0, perc[k], wA.x);
                fma2(a1, perc[k], wA.y);
                fma2(a2, perc[k], wB.x);
                fma2(a3, perc[k], wB.y);
            }
            ULL h[4];
            h[0] = relu2(a0); h[1] = relu2(a1); h[2] = relu2(a2); h[3] = relu2(a3);
            #pragma unroll
            for (int q = 0; q < 4; q++) {
                const ULL* w2r = sw2 + (ob + q)*16;
                ULL hq = h[q];
                #pragma unroll
                for (int j = 0; j < 16; j += 2) {
                    ulonglong2 w = *reinterpret_cast<const ulonglong2*>(w2r + j);
                    fma2(cur[j],   hq, w.x);
                    fma2(cur[j+1], hq, w.y);
                }
            }
        }

        // ---- store cur (packed) + pre mask ----
        const int gy = gy0 + r, gx = gx0 + 2*ix;
        size_t base = (((size_t)n*CCH)*Hh + gy)*Ww + gx;
        #pragma unroll
        for (int j = 0; j < 16; j++) {
            *reinterpret_cast<ULL*>(dst + base + (size_t)j*Hh*Ww) = cur[j];
        }
        int pb = (n*Hh + gy)*Ww + gx;
        uchar2 pm;
        pm.x = (premax_lo > 0.1f) ? 1 : 0;
        pm.y = (premax_hi > 0.1f) ? 1 : 0;
        *reinterpret_cast<uchar2*>(g_pre + pb) = pm;
    }
}

// Kernel 2: post mask (3x3 maxpool of new cur ch0) & alive byte; last iter writes output.
__global__ void alive_kernel(float* __restrict__ outfinal, int parity, int writeOut)
{
    const float* __restrict__ cur = parity ? g_bufA : g_bufB;  // buffer step just wrote
    int p = blockIdx.x*blockDim.x + threadIdx.x;   // over NB*Hh*Ww
    if (p >= NB*Hh*Ww) return;
    int x = p % Ww;
    int y = (p / Ww) % Hh;
    int n = p / (Hh*Ww);
    const float* c0 = cur + (size_t)n*CCH*Hh*Ww;
    float m = -1e30f;
    #pragma unroll
    for (int dy = -1; dy <= 1; dy++) {
        int yy = y + dy;
        if (yy < 0 || yy >= Hh) continue;
        const float* row = c0 + yy*Ww;
        #pragma unroll
        for (int dx = -1; dx <= 1; dx++) {
            int xx = x + dx;
            if (xx < 0 || xx >= Ww) continue;
            m = fmaxf(m, row[xx]);
        }
    }
    bool alive = (m > 0.1f) && (g_pre[p] != 0);
    g_alive[p] = alive ? 1 : 0;
    if (writeOut) {
        size_t base = ((size_t)n*CCH)*Hh*Ww + (size_t)y*Ww + x;
        #pragma unroll
        for (int c = 1; c <= 10; c++) {
            float v = alive ? cur[base + (size_t)c*Hh*Ww] : 0.0f;
            outfinal[(((size_t)n*10 + (c-1))*Hh + y)*Ww + x] = v;
        }
    }
}

extern "C" void kernel_launch(void* const* d_in, const int* in_sizes, int n_in,
                              void* d_out, int out_size)
{
    const float *inp = nullptr, *w1 = nullptr, *w2 = nullptr;
    for (int i = 0; i < n_in; i++) {
        if (in_sizes[i] == 48*48)      w1 = (const float*)d_in[i];
        else if (in_sizes[i] == 16*48) w2 = (const float*)d_in[i];
        else                           inp = (const float*)d_in[i];
    }
    float* out = (float*)d_out;

    const int smemBytes = (CCH*IH*IWP)*4 + (48*48 + 48*16)*8;  // 40320 + 24576 = 64896
    cudaFuncSetAttribute(step_kernel, cudaFuncAttributeMaxDynamicSharedMemorySize, smemBytes);

    init_kernel<<<(NB*CCH*Hh*Ww + 255)/256, 256>>>(inp);

    dim3 g1(Ww/TW, Hh/TH, NB);   // (4, 8, 32)
    const int g2 = (NB*Hh*Ww + 255)/256;
    for (int it = 0; it < NITER; it++) {
        int parity = it & 1;   // src = buf[parity], dst = buf[parity^1]
        step_kernel<<<g1, 128, smemBytes>>>(w1, w2, parity);
        alive_kernel<<<g2, 256>>>(out, parity, (it == NITER-1) ? 1 : 0);
    }
}

// round 4
// speedup vs baseline: 1.0803x; 1.0803x over previous
#include <cuda_runtime.h>

#define Hh 128
#define Ww 128
#define NB 32
#define CCH 16
#define NITER 30

#define TW 32
#define TH 16
#define IW 34
#define IH 18
#define IWP 35   // padded smem row

typedef unsigned long long ULL;

// persistent state (no allocation allowed) — double buffered to avoid intra-launch RAW race
__device__ float g_bufA[NB*CCH*Hh*Ww];
__device__ float g_bufB[NB*CCH*Hh*Ww];
__device__ unsigned char g_pre[NB*Hh*Ww];      // pre-mask of current iter
__device__ unsigned char g_alive[NB*Hh*Ww];    // pre & post mask (applied lazily)

__device__ __forceinline__ ULL pk2(float a, float b){
    ULL r; asm("mov.b64 %0, {%1,%2};" : "=l"(r) : "f"(a), "f"(b)); return r;
}
__device__ __forceinline__ void fma2(ULL &d, ULL a, ULL b){
    asm("fma.rn.f32x2 %0, %1, %2, %0;" : "+l"(d) : "l"(a), "l"(b));
}
__device__ __forceinline__ float lo2(ULL v){ return __uint_as_float((unsigned)v); }
__device__ __forceinline__ float hi2(ULL v){ return __uint_as_float((unsigned)(v>>32)); }
__device__ __forceinline__ ULL relu2(ULL v){
    return pk2(fmaxf(lo2(v), 0.f), fmaxf(hi2(v), 0.f));
}

// Build initial state into bufA: cell, alive = 1
__global__ void init_kernel(const float* __restrict__ inp){
    int p = blockIdx.x*blockDim.x + threadIdx.x;
    const int total = NB*CCH*Hh*Ww;
    if (p >= total) return;
    int hw = p % (Hh*Ww);
    int c  = (p / (Hh*Ww)) % CCH;
    int n  = p / (CCH*Hh*Ww);
    float v;
    if (c == 0)       v = 1.0f - inp[(n*10 + 0)*Hh*Ww + hw];
    else if (c <= 10) v = inp[(n*10 + (c-1))*Hh*Ww + hw];
    else              v = 0.0f;
    g_bufA[p] = v;
    if (c == 0) g_alive[n*Hh*Ww + hw] = 1;
}

// Kernel 1: cell = src*alive (tile), perception + W1(relu) + W2 + residual -> dst; pre-mask byte.
__global__ void __launch_bounds__(128, 3)
step_kernel(const float* __restrict__ w1, const float* __restrict__ w2, int parity)
{
    extern __shared__ float smem[];
    float* sc = smem;                               // 16*18*35 floats
    ULL* sw1 = (ULL*)(smem + CCH*IH*IWP);           // [k][o] splatted pairs, 2304
    ULL* sw2 = sw1 + 48*48;                         // [o][j] splatted pairs, 768

    const float* __restrict__ src = parity ? g_bufB : g_bufA;
    float* __restrict__ dst       = parity ? g_bufA : g_bufB;

    const int tid = threadIdx.x;
    const int bx = blockIdx.x, by = blockIdx.y, n = blockIdx.z;
    const int gx0 = bx*TW, gy0 = by*TH;

    // w1 transposed+splatted: sw1[k*48+o] = (w1[o][k], w1[o][k])
    for (int i = tid; i < 48*48; i += 128) {
        int k = i / 48, o = i % 48;
        float w = w1[o*48 + k];
        sw1[i] = pk2(w, w);
    }
    // w2 transposed+splatted: sw2[o*16+j] = (w2[j][o], w2[j][o])
    for (int i = tid; i < 48*16; i += 128) {
        int o = i >> 4, j = i & 15;
        float w = w2[j*48 + o];
        sw2[i] = pk2(w, w);
    }
    // load masked cell tile with 1-pixel halo (zero padded)
    for (int i = tid; i < CCH*IH*IW; i += 128) {
        int sx = i % IW;
        int sy = (i / IW) % IH;
        int c  = i / (IW*IH);
        int gx = gx0 + sx - 1, gy = gy0 + sy - 1;
        float v = 0.0f;
        if (gx >= 0 && gx < Ww && gy >= 0 && gy < Hh) {
            int hw = gy*Ww + gx;
            if (g_alive[n*Hh*Ww + hw])
                v = src[((size_t)(n*CCH + c)*Hh)*Ww + hw];
        }
        sc[(c*IH + sy)*IWP + sx] = v;
    }
    __syncthreads();

    #pragma unroll 1
    for (int pass = 0; pass < 2; pass++) {
        const int pp = tid + pass*128;     // 0..255 pixel-pairs
        const int r  = pp >> 4;            // tile row 0..15
        const int ix = pp & 15;            // pair index (x0 = 2*ix)
        const int sy = r + 1;
        const int sx = 2*ix + 1;

        // ---- perception: 48 packed channels (cell, sobel-x, sobel-y) ----
        ULL perc[48];
        float premax_lo = -1e30f, premax_hi = -1e30f;
        #pragma unroll
        for (int c = 0; c < CCH; c++) {
            const float* b0 = sc + (c*IH + (sy-1))*IWP + (sx-1);
            const float* b1 = b0 + IWP;
            const float* b2 = b1 + IWP;
            float a0=b0[0],a1=b0[1],a2=b0[2],a3=b0[3];
            float m0=b1[0],m1=b1[1],m2=b1[2],m3=b1[3];
            float q0=b2[0],q1=b2[1],q2=b2[2],q3=b2[3];
            float gxl = ((a2 - a0) + 2.f*(m2 - m0) + (q2 - q0)) * 0.125f;
            float gxh = ((a3 - a1) + 2.f*(m3 - m1) + (q3 - q1)) * 0.125f;
            float gyl = ((q0 - a0) + 2.f*(q1 - a1) + (q2 - a2)) * 0.125f;
            float gyh = ((q1 - a1) + 2.f*(q2 - a2) + (q3 - a3)) * 0.125f;
            perc[c]      = pk2(m1, m2);
            perc[16 + c] = pk2(gxl, gxh);
            perc[32 + c] = pk2(gyl, gyh);
            if (c == 0) {
                float t0 = fmaxf(fmaxf(a0,a1),a2);
                float t1 = fmaxf(fmaxf(m0,m1),m2);
                float t2 = fmaxf(fmaxf(q0,q1),q2);
                premax_lo = fmaxf(fmaxf(t0,t1),t2);
                float u0 = fmaxf(fmaxf(a1,a2),a3);
                float u1 = fmaxf(fmaxf(m1,m2),m3);
                float u2 = fmaxf(fmaxf(q1,q2),q3);
                premax_hi = fmaxf(fmaxf(u0,u1),u2);
            }
        }

        // ---- cur = W2 * relu(W1 * perc) + cell, fully packed f32x2 ----
        ULL cur[16];
        #pragma unroll
        for (int j = 0; j < 16; j++) cur[j] = perc[j];   // residual init

        for (int ob = 0; ob < 48; ob += 2) {
            ULL a0 = 0ull, a1 = 0ull;
            #pragma unroll
            for (int k = 0; k < 48; k++) {
                ulonglong2 w = *reinterpret_cast<const ulonglong2*>(sw1 + k*48 + ob);
                fma2(a0, perc[k], w.x);
                fma2(a1, perc[k], w.y);
            }
            ULL h0 = relu2(a0), h1 = relu2(a1);
            const ULL* w2r = sw2 + ob*16;
            #pragma unroll
            for (int j = 0; j < 16; j += 2) {
                ulonglong2 wa = *reinterpret_cast<const ulonglong2*>(w2r + j);
                ulonglong2 wb = *reinterpret_cast<const ulonglong2*>(w2r + 16 + j);
                fma2(cur[j],   h0, wa.x);
                fma2(cur[j+1], h0, wa.y);
                fma2(cur[j],   h1, wb.x);
                fma2(cur[j+1], h1, wb.y);
            }
        }

        // ---- store cur (packed) + pre mask ----
        const int gy = gy0 + r, gx = gx0 + 2*ix;
        size_t base = (((size_t)n*CCH)*Hh + gy)*Ww + gx;
        #pragma unroll
        for (int j = 0; j < 16; j++) {
            *reinterpret_cast<ULL*>(dst + base + (size_t)j*Hh*Ww) = cur[j];
        }
        int pb = (n*Hh + gy)*Ww + gx;
        uchar2 pm;
        pm.x = (premax_lo > 0.1f) ? 1 : 0;
        pm.y = (premax_hi > 0.1f) ? 1 : 0;
        *reinterpret_cast<uchar2*>(g_pre + pb) = pm;
    }
}

// Kernel 2: post mask (3x3 maxpool of new cur ch0) & alive byte; last iter writes output.
__global__ void alive_kernel(float* __restrict__ outfinal, int parity, int writeOut)
{
    const float* __restrict__ cur = parity ? g_bufA : g_bufB;  // buffer step just wrote
    int p = blockIdx.x*blockDim.x + threadIdx.x;   // over NB*Hh*Ww
    if (p >= NB*Hh*Ww) return;
    int x = p % Ww;
    int y = (p / Ww) % Hh;
    int n = p / (Hh*Ww);
    const float* c0 = cur + (size_t)n*CCH*Hh*Ww;
    float m = -1e30f;
    #pragma unroll
    for (int dy = -1; dy <= 1; dy++) {
        int yy = y + dy;
        if (yy < 0 || yy >= Hh) continue;
        const float* row = c0 + yy*Ww;
        #pragma unroll
        for (int dx = -1; dx <= 1; dx++) {
            int xx = x + dx;
            if (xx < 0 || xx >= Ww) continue;
            m = fmaxf(m, row[xx]);
        }
    }
    bool alive = (m > 0.1f) && (g_pre[p] != 0);
    g_alive[p] = alive ? 1 : 0;
    if (writeOut) {
        size_t base = ((size_t)n*CCH)*Hh*Ww + (size_t)y*Ww + x;
        #pragma unroll
        for (int c = 1; c <= 10; c++) {
            float v = alive ? cur[base + (size_t)c*Hh*Ww] : 0.0f;
            outfinal[(((size_t)n*10 + (c-1))*Hh + y)*Ww + x] = v;
        }
    }
}

extern "C" void kernel_launch(void* const* d_in, const int* in_sizes, int n_in,
                              void* d_out, int out_size)
{
    const float *inp = nullptr, *w1 = nullptr, *w2 = nullptr;
    for (int i = 0; i < n_in; i++) {
        if (in_sizes[i] == 48*48)      w1 = (const float*)d_in[i];
        else if (in_sizes[i] == 16*48) w2 = (const float*)d_in[i];
        else                           inp = (const float*)d_in[i];
    }
    float* out = (float*)d_out;

    const int smemBytes = (CCH*IH*IWP)*4 + (48*48 + 48*16)*8;  // 40320 + 24576 = 64896
    cudaFuncSetAttribute(step_kernel, cudaFuncAttributeMaxDynamicSharedMemorySize, smemBytes);

    init_kernel<<<(NB*CCH*Hh*Ww + 255)/256, 256>>>(inp);

    dim3 g1(Ww/TW, Hh/TH, NB);   // (4, 8, 32)
    const int g2 = (NB*Hh*Ww + 255)/256;
    for (int it = 0; it < NITER; it++) {
        int parity = it & 1;   // src = buf[parity], dst = buf[parity^1]
        step_kernel<<<g1, 128, smemBytes>>>(w1, w2, parity);
        alive_kernel<<<g2, 256>>>(out, parity, (it == NITER-1) ? 1 : 0);
    }
}

// round 5
// speedup vs baseline: 1.3415x; 1.2417x over previous
#include <cuda_runtime.h>

#define Hh 128
#define Ww 128
#define NB 32
#define CCH 16
#define NITER 30

#define TW 16
#define TH 16
#define IW 18
#define IH 18
#define IWP 19   // padded smem col stride

typedef unsigned long long ULL;

// persistent state — double buffered (intra-launch halo race avoidance)
__device__ float g_bufA[NB*CCH*Hh*Ww];
__device__ float g_bufB[NB*CCH*Hh*Ww];
__device__ unsigned char g_pre[NB*Hh*Ww];
__device__ unsigned char g_alive[NB*Hh*Ww];

__device__ __forceinline__ ULL pk2(float a, float b){
    ULL r; asm("mov.b64 %0, {%1,%2};" : "=l"(r) : "f"(a), "f"(b)); return r;
}
__device__ __forceinline__ void fma2(ULL &d, ULL a, ULL b){
    asm("fma.rn.f32x2 %0, %1, %2, %0;" : "+l"(d) : "l"(a), "l"(b));
}
__device__ __forceinline__ float lo2(ULL v){ return __uint_as_float((unsigned)v); }
__device__ __forceinline__ float hi2(ULL v){ return __uint_as_float((unsigned)(v>>32)); }
__device__ __forceinline__ ULL relu2(ULL v){
    return pk2(fmaxf(lo2(v), 0.f), fmaxf(hi2(v), 0.f));
}

__global__ void init_kernel(const float* __restrict__ inp){
    int p = blockIdx.x*blockDim.x + threadIdx.x;
    const int total = NB*CCH*Hh*Ww;
    if (p >= total) return;
    int hw = p % (Hh*Ww);
    int c  = (p / (Hh*Ww)) % CCH;
    int n  = p / (CCH*Hh*Ww);
    float v;
    if (c == 0)       v = 1.0f - inp[(n*10 + 0)*Hh*Ww + hw];
    else if (c <= 10) v = inp[(n*10 + (c-1))*Hh*Ww + hw];
    else              v = 0.0f;
    g_bufA[p] = v;
    if (c == 0) g_alive[n*Hh*Ww + hw] = 1;
}

// smem ULL layout:
//   sw1:  [0, 2304)       w1 splatted [k][o]
//   sw2:  [2304, 3072)    w2 splatted [o][j]
//   sp:   [3072, 9216)    perc [48][128]; rows 16..47 reused as H rows 16..47
//   hlo:  [9216, 11264)   H rows 0..15 [16][128]; start aliased as alive tile bytes
//   sc:   floats at ULL 11264: 16*18*19 floats
__global__ void __launch_bounds__(256, 2)
step_kernel(const float* __restrict__ w1, const float* __restrict__ w2, int parity)
{
    extern __shared__ ULL smem_u[];
    ULL* sw1 = smem_u;
    ULL* sw2 = smem_u + 2304;
    ULL* sp  = smem_u + 3072;
    ULL* hlo = smem_u + 9216;
    float* sc = (float*)(smem_u + 11264);
    unsigned char* sa = (unsigned char*)hlo;   // alive tile (dead before H is written)

    const float* __restrict__ src = parity ? g_bufB : g_bufA;
    float* __restrict__ dst       = parity ? g_bufA : g_bufB;

    const int tid = threadIdx.x;
    const int n = blockIdx.z;
    const int gx0 = blockIdx.x*TW, gy0 = blockIdx.y*TH;

    // ---- stage 0: weights + alive tile + masked cell tile ----
    for (int i = tid; i < 48*48; i += 256) {
        int k = i / 48, o = i % 48;
        float w = w1[o*48 + k];
        sw1[i] = pk2(w, w);
    }
    for (int i = tid; i < 48*16; i += 256) {
        int o = i >> 4, j = i & 15;
        float w = w2[j*48 + o];
        sw2[i] = pk2(w, w);
    }
    for (int i = tid; i < IW*IH; i += 256) {
        int sx = i % IW, sy = i / IW;
        int gx = gx0 + sx - 1, gy = gy0 + sy - 1;
        unsigned char a = 0;
        if (gx >= 0 && gx < Ww && gy >= 0 && gy < Hh)
            a = g_alive[(n*Hh + gy)*Ww + gx];
        sa[i] = a;
    }
    __syncthreads();
    for (int i = tid; i < CCH*IH*IW; i += 256) {
        int sx = i % IW;
        int t  = i / IW;
        int sy = t % IH;
        int c  = t / IH;
        int gx = gx0 + sx - 1, gy = gy0 + sy - 1;
        float v = 0.0f;
        if (gx >= 0 && gx < Ww && gy >= 0 && gy < Hh && sa[sy*IW + sx])
            v = src[(((size_t)n*CCH + c)*Hh + gy)*Ww + gx];
        sc[(c*IH + sy)*IWP + sx] = v;
    }
    __syncthreads();

    // ---- stage 1: perception -> sp (2 threads per pair, 8 channels each) ----
    {
        const int pair = tid & 127;
        const int half = tid >> 7;
        const int py = pair >> 3, px2 = pair & 7;
        const int sy = py + 1, sx = 2*px2 + 1;
        #pragma unroll
        for (int cc = 0; cc < 8; cc++) {
            int c = half*8 + cc;
            const float* b0 = sc + (c*IH + (sy-1))*IWP + (sx-1);
            const float* b1 = b0 + IWP;
            const float* b2 = b1 + IWP;
            float a0=b0[0],a1=b0[1],a2=b0[2],a3=b0[3];
            float m0=b1[0],m1=b1[1],m2=b1[2],m3=b1[3];
            float q0=b2[0],q1=b2[1],q2=b2[2],q3=b2[3];
            float gxl = ((a2 - a0) + 2.f*(m2 - m0) + (q2 - q0)) * 0.125f;
            float gxh = ((a3 - a1) + 2.f*(m3 - m1) + (q3 - q1)) * 0.125f;
            float gyl = ((q0 - a0) + 2.f*(q1 - a1) + (q2 - a2)) * 0.125f;
            float gyh = ((q1 - a1) + 2.f*(q2 - a2) + (q3 - a3)) * 0.125f;
            sp[c*128 + pair]        = pk2(m1, m2);
            sp[(16 + c)*128 + pair] = pk2(gxl, gxh);
            sp[(32 + c)*128 + pair] = pk2(gyl, gyh);
            if (c == 0) {
                float t0 = fmaxf(fmaxf(a0,a1),a2);
                float t1 = fmaxf(fmaxf(m0,m1),m2);
                float t2 = fmaxf(fmaxf(q0,q1),q2);
                float pl = fmaxf(fmaxf(t0,t1),t2);
                float u0 = fmaxf(fmaxf(a1,a2),a3);
                float u1 = fmaxf(fmaxf(m1,m2),m3);
                float u2 = fmaxf(fmaxf(q1,q2),q3);
                float ph = fmaxf(fmaxf(u0,u1),u2);
                uchar2 pm;
                pm.x = (pl > 0.1f) ? 1 : 0;
                pm.y = (ph > 0.1f) ? 1 : 0;
                *reinterpret_cast<uchar2*>(g_pre + (n*Hh + gy0 + py)*Ww + gx0 + 2*px2) = pm;
            }
        }
    }
    __syncthreads();

    // ---- GEMM1: H = relu(W1 * perc), thread = (pair-lane g, o-block b) ----
    {
        const int g = tid & 31;   // pairs g, g+32, g+64, g+96
        const int b = tid >> 5;   // o = 6b .. 6b+5
        ULL acc[4][6];
        #pragma unroll
        for (int i = 0; i < 4; i++)
            #pragma unroll
            for (int j = 0; j < 6; j++) acc[i][j] = 0ull;

        #pragma unroll 8
        for (int k = 0; k < 48; k++) {
            ULL p0 = sp[k*128 + g];
            ULL p1 = sp[k*128 + g + 32];
            ULL p2 = sp[k*128 + g + 64];
            ULL p3 = sp[k*128 + g + 96];
            const ULL* wr = sw1 + k*48 + 6*b;
            ulonglong2 wA = *reinterpret_cast<const ulonglong2*>(wr);
            ulonglong2 wB = *reinterpret_cast<const ulonglong2*>(wr + 2);
            ulonglong2 wC = *reinterpret_cast<const ulonglong2*>(wr + 4);
            fma2(acc[0][0], p0, wA.x); fma2(acc[1][0], p1, wA.x); fma2(acc[2][0], p2, wA.x); fma2(acc[3][0], p3, wA.x);
            fma2(acc[0][1], p0, wA.y); fma2(acc[1][1], p1, wA.y); fma2(acc[2][1], p2, wA.y); fma2(acc[3][1], p3, wA.y);
            fma2(acc[0][2], p0, wB.x); fma2(acc[1][2], p1, wB.x); fma2(acc[2][2], p2, wB.x); fma2(acc[3][2], p3, wB.x);
            fma2(acc[0][3], p0, wB.y); fma2(acc[1][3], p1, wB.y); fma2(acc[2][3], p2, wB.y); fma2(acc[3][3], p3, wB.y);
            fma2(acc[0][4], p0, wC.x); fma2(acc[1][4], p1, wC.x); fma2(acc[2][4], p2, wC.x); fma2(acc[3][4], p3, wC.x);
            fma2(acc[0][5], p0, wC.y); fma2(acc[1][5], p1, wC.y); fma2(acc[2][5], p2, wC.y); fma2(acc[3][5], p3, wC.y);
        }
        __syncthreads();   // all sp reads complete before H overwrites rows 16..47
        #pragma unroll
        for (int oo = 0; oo < 6; oo++) {
            int o = 6*b + oo;
            ULL* hr = (o < 16) ? (hlo + o*128) : (sp + o*128);
            hr[g]      = relu2(acc[0][oo]);
            hr[g + 32] = relu2(acc[1][oo]);
            hr[g + 64] = relu2(acc[2][oo]);
            hr[g + 96] = relu2(acc[3][oo]);
        }
    }
    __syncthreads();

    // ---- GEMM2: cur = W2 * H + cell, thread = (pair g2/g2+64, j-block jb) ----
    {
        const int g2 = tid & 63;
        const int jb = tid >> 6;   // j = 4jb .. 4jb+3
        ULL c0[4], c1[4];
        #pragma unroll
        for (int jj = 0; jj < 4; jj++) {
            int j = 4*jb + jj;
            c0[jj] = sp[j*128 + g2];        // residual: cell rows preserved in sp[0..15]
            c1[jj] = sp[j*128 + g2 + 64];
        }
        #pragma unroll 8
        for (int o = 0; o < 48; o++) {
            const ULL* hr = (o < 16) ? (hlo + o*128) : (sp + o*128);
            ULL h0 = hr[g2];
            ULL h1 = hr[g2 + 64];
            const ULL* wr = sw2 + o*16 + 4*jb;
            ulonglong2 wA = *reinterpret_cast<const ulonglong2*>(wr);
            ulonglong2 wB = *reinterpret_cast<const ulonglong2*>(wr + 2);
            fma2(c0[0], h0, wA.x); fma2(c0[1], h0, wA.y); fma2(c0[2], h0, wB.x); fma2(c0[3], h0, wB.y);
            fma2(c1[0], h1, wA.x); fma2(c1[1], h1, wA.y); fma2(c1[2], h1, wB.x); fma2(c1[3], h1, wB.y);
        }
        // store
        const int py0 = g2 >> 3,        px0 = g2 & 7;
        const int py1 = (g2 + 64) >> 3, px1 = (g2 + 64) & 7;
        #pragma unroll
        for (int jj = 0; jj < 4; jj++) {
            int j = 4*jb + jj;
            size_t basej = (((size_t)n*CCH + j)*Hh)*Ww;
            *reinterpret_cast<ULL*>(dst + basej + (size_t)(gy0 + py0)*Ww + gx0 + 2*px0) = c0[jj];
            *reinterpret_cast<ULL*>(dst + basej + (size_t)(gy0 + py1)*Ww + gx0 + 2*px1) = c1[jj];
        }
    }
}

// post mask (3x3 maxpool of new cur ch0) & alive byte; last iter writes output.
__global__ void alive_kernel(float* __restrict__ outfinal, int parity, int writeOut)
{
    const float* __restrict__ cur = parity ? g_bufA : g_bufB;
    int p = blockIdx.x*blockDim.x + threadIdx.x;
    if (p >= NB*Hh*Ww) return;
    int x = p % Ww;
    int y = (p / Ww) % Hh;
    int n = p / (Hh*Ww);
    const float* c0 = cur + (size_t)n*CCH*Hh*Ww;
    float m = -1e30f;
    #pragma unroll
    for (int dy = -1; dy <= 1; dy++) {
        int yy = y + dy;
        if (yy < 0 || yy >= Hh) continue;
        const float* row = c0 + yy*Ww;
        #pragma unroll
        for (int dx = -1; dx <= 1; dx++) {
            int xx = x + dx;
            if (xx < 0 || xx >= Ww) continue;
            m = fmaxf(m, row[xx]);
        }
    }
    bool alive = (m > 0.1f) && (g_pre[p] != 0);
    g_alive[p] = alive ? 1 : 0;
    if (writeOut) {
        size_t base = ((size_t)n*CCH)*Hh*Ww + (size_t)y*Ww + x;
        #pragma unroll
        for (int c = 1; c <= 10; c++) {
            float v = alive ? cur[base + (size_t)c*Hh*Ww] : 0.0f;
            outfinal[(((size_t)n*10 + (c-1))*Hh + y)*Ww + x] = v;
        }
    }
}

extern "C" void kernel_launch(void* const* d_in, const int* in_sizes, int n_in,
                              void* d_out, int out_size)
{
    const float *inp = nullptr, *w1 = nullptr, *w2 = nullptr;
    for (int i = 0; i < n_in; i++) {
        if (in_sizes[i] == 48*48)      w1 = (const float*)d_in[i];
        else if (in_sizes[i] == 16*48) w2 = (const float*)d_in[i];
        else                           inp = (const float*)d_in[i];
    }
    float* out = (float*)d_out;

    // 11264 ULL (weights+sp+hlo) + 16*18*19 floats
    const int smemBytes = 11264*8 + CCH*IH*IWP*4;   // 90112 + 21888 = 112000
    cudaFuncSetAttribute(step_kernel, cudaFuncAttributeMaxDynamicSharedMemorySize, smemBytes);

    init_kernel<<<(NB*CCH*Hh*Ww + 255)/256, 256>>>(inp);

    dim3 g1(Ww/TW, Hh/TH, NB);   // (8, 8, 32)
    const int g2 = (NB*Hh*Ww + 255)/256;
    for (int it = 0; it < NITER; it++) {
        int parity = it & 1;
        step_kernel<<<g1, 256, smemBytes>>>(w1, w2, parity);
        alive_kernel<<<g2, 256>>>(out, parity, (it == NITER-1) ? 1 : 0);
    }
}